// round 12
// baseline (speedup 1.0000x reference)
#include <cuda_runtime.h>
#include <cstdint>

#define D_MODEL 1024
#define NHEAD   16
#define DK      64
#define SEQ     2048
#define BATCH   4
#define MROWS   (BATCH * SEQ)   // 8192

// ---------------------------------------------------------------------------
// Scratch (allocation-free rule: __device__ globals)
// ---------------------------------------------------------------------------
__device__ float g_Q[BATCH * NHEAD * SEQ * DK];   // [B,H,n,dk], tf32-rounded
__device__ float g_K[BATCH * NHEAD * SEQ * DK];
__device__ float g_V[BATCH * NHEAD * SEQ * DK];
__device__ float g_AO[BATCH * SEQ * D_MODEL];     // attention out, [B,n,D], tf32-rounded
__device__ float g_Xc[MROWS * D_MODEL];           // tf32-rounded X
__device__ float g_Wqc[D_MODEL * D_MODEL];
__device__ float g_Wkc[D_MODEL * D_MODEL];
__device__ float g_Wvc[D_MODEL * D_MODEL];
__device__ float g_Woc[D_MODEL * D_MODEL];

// ---------------------------------------------------------------------------
// helpers
// ---------------------------------------------------------------------------
__device__ __forceinline__ uint32_t smem_u32(const void* p) {
    uint32_t a;
    asm("{ .reg .u64 t; cvta.to.shared.u64 t, %1; cvt.u32.u64 %0, t; }"
        : "=r"(a) : "l"(p));
    return a;
}

__device__ __forceinline__ void cp_async16(uint32_t dst, const void* src) {
    asm volatile("cp.async.cg.shared.global [%0], [%1], 16;\n" :: "r"(dst), "l"(src));
}
#define CP_COMMIT()  asm volatile("cp.async.commit_group;\n" ::: "memory")
#define CP_WAIT(N)   asm volatile("cp.async.wait_group %0;\n" :: "n"(N) : "memory")

__device__ __forceinline__ void mma_tf32(float* c, const float* a, const float* b) {
    asm volatile(
        "mma.sync.aligned.m16n8k8.row.col.f32.tf32.tf32.f32 "
        "{%0,%1,%2,%3}, {%4,%5,%6,%7}, {%8,%9}, {%0,%1,%2,%3};"
        : "+f"(c[0]), "+f"(c[1]), "+f"(c[2]), "+f"(c[3])
        : "r"(__float_as_uint(a[0])), "r"(__float_as_uint(a[1])),
          "r"(__float_as_uint(a[2])), "r"(__float_as_uint(a[3])),
          "r"(__float_as_uint(b[0])), "r"(__float_as_uint(b[1])));
}

__device__ __forceinline__ float rna_tf32(float x) {
    uint32_t u;
    asm("cvt.rna.tf32.f32 %0, %1;" : "=r"(u) : "f"(x));
    return __uint_as_float(u);
}

// ---------------------------------------------------------------------------
// Elementwise tf32 RNA rounding (unbiased).
// ---------------------------------------------------------------------------
__global__ void round_tf32(const float* __restrict__ in, float* __restrict__ out, int n4) {
    int i = blockIdx.x * blockDim.x + threadIdx.x;
    if (i < n4) {
        float4 v = ((const float4*)in)[i];
        float4 o;
        o.x = rna_tf32(v.x); o.y = rna_tf32(v.y);
        o.z = rna_tf32(v.z); o.w = rna_tf32(v.w);
        ((float4*)out)[i] = o;
    }
}

// ---------------------------------------------------------------------------
// TN GEMM on mma.sync tf32: C[m,n] = sum_k A[m,k] * W[n,k] + bias[n]
// CTA tile 128x128, 128 threads = 4 warps (2x2), warp tile 64x64, BK=32.
// => 128 mma + 128 LDS per warp between barriers (flash-like ratio).
// 2-stage cp.async, 2 barriers per chunk, 32 chunks.
// Smem row stride 36 (== 4 mod 32): fragment lanes hit banks 4*grp+tig,
// conflict-free. 2 CTAs/SM at 73.7KB dynamic smem.
// HEADOUT writes C into [B,H,n,dk] layout, RNA-rounded to tf32.
// ---------------------------------------------------------------------------
#define GPAD 36
#define GBK  32
#define G_AST (128 * GPAD)                // 4608 floats: A region per stage
#define G_STG (2 * G_AST)                 // 9216 floats: A+B per stage
#define G_SMEM (2 * G_STG * 4)            // 73728 bytes

template <bool HEADOUT>
__global__ void __launch_bounds__(128) gemm_tf32mma(
    const float* __restrict__ A, const float* __restrict__ W,
    const float* __restrict__ bias, float* __restrict__ C)
{
    extern __shared__ float sm[];

    const int K = D_MODEL;
    const int tid = threadIdx.x;
    const int wid = tid >> 5;
    const int lid = tid & 31;
    const int warpM = wid >> 1;            // 0..1
    const int warpN = wid & 1;             // 0..1
    const int grp = lid >> 2;              // 0..7
    const int tig = lid & 3;               // 0..3
    const int row0 = blockIdx.y * 128;
    const int col0 = blockIdx.x * 128;

    const uint32_t base = smem_u32(sm);

    // loaders: thread t owns row t of the A tile and row t of the B tile;
    // per chunk each loads its row's 32 floats (8 x cp.async16).
    const float* Ath = A + (size_t)(row0 + tid) * K;
    const float* Wth = W + (size_t)(col0 + tid) * K;
    const uint32_t rowDst = (uint32_t)(tid * GPAD) * 4;   // 144B-aligned

    float acc[4][8][4];
#pragma unroll
    for (int mt = 0; mt < 4; mt++)
#pragma unroll
        for (int nt = 0; nt < 8; nt++)
#pragma unroll
            for (int j = 0; j < 4; j++) acc[mt][nt][j] = 0.0f;

    // preload chunk 0 -> stage 0
    {
        const uint32_t a0 = base;
        const uint32_t b0 = base + (uint32_t)G_AST * 4;
#pragma unroll
        for (int j = 0; j < 8; j++) {
            cp_async16(a0 + rowDst + j * 16, Ath + j * 4);
            cp_async16(b0 + rowDst + j * 16, Wth + j * 4);
        }
        CP_COMMIT();
    }

    const int NC = K / GBK;   // 32
#pragma unroll 1
    for (int c = 0; c < NC; c++) {
        const int s = c & 1;
        if (c + 1 < NC) {
            // stage s^1 held chunk c-1; its readers finished before the
            // end-of-compute barrier of the previous iteration.
            const uint32_t a0 = base + (uint32_t)((s ^ 1) * G_STG) * 4;
            const uint32_t b0 = a0 + (uint32_t)G_AST * 4;
            const int k0 = (c + 1) * GBK;
#pragma unroll
            for (int j = 0; j < 8; j++) {
                cp_async16(a0 + rowDst + j * 16, Ath + k0 + j * 4);
                cp_async16(b0 + rowDst + j * 16, Wth + k0 + j * 4);
            }
            CP_COMMIT();
            CP_WAIT(1);     // chunk c resident
        } else {
            CP_WAIT(0);
        }
        __syncthreads();

        const float* Ab = sm + s * G_STG;
        const float* Bb = Ab + G_AST;
#pragma unroll
        for (int ks = 0; ks < 4; ks++) {
            const int kb = ks * 8;
            float af[4][4];
#pragma unroll
            for (int mt = 0; mt < 4; mt++) {
                const int rb = warpM * 64 + mt * 16;
                af[mt][0] = Ab[(rb + grp)     * GPAD + kb + tig];
                af[mt][1] = Ab[(rb + grp + 8) * GPAD + kb + tig];
                af[mt][2] = Ab[(rb + grp)     * GPAD + kb + tig + 4];
                af[mt][3] = Ab[(rb + grp + 8) * GPAD + kb + tig + 4];
            }
            float bf[8][2];
#pragma unroll
            for (int nt = 0; nt < 8; nt++) {
                const int cb = warpN * 64 + nt * 8;
                bf[nt][0] = Bb[(cb + grp) * GPAD + kb + tig];
                bf[nt][1] = Bb[(cb + grp) * GPAD + kb + tig + 4];
            }
#pragma unroll
            for (int mt = 0; mt < 4; mt++)
#pragma unroll
                for (int nt = 0; nt < 8; nt++)
                    mma_tf32(acc[mt][nt], af[mt], bf[nt]);
        }
        __syncthreads();    // all reads of chunk c done
    }

    // epilogue
#pragma unroll
    for (int mt = 0; mt < 4; mt++) {
#pragma unroll
        for (int nt = 0; nt < 8; nt++) {
            const int r  = row0 + warpM * 64 + mt * 16 + grp;
            const int cc = col0 + warpN * 64 + nt * 8 + tig * 2;
            const float2 bb = *(const float2*)(bias + cc);

            float2 v01 = make_float2(acc[mt][nt][0] + bb.x, acc[mt][nt][1] + bb.y);
            float2 v23 = make_float2(acc[mt][nt][2] + bb.x, acc[mt][nt][3] + bb.y);

            if (HEADOUT) {
                // RNA-round so flash's tf32 mma truncation is exact.
                v01.x = rna_tf32(v01.x); v01.y = rna_tf32(v01.y);
                v23.x = rna_tf32(v23.x); v23.y = rna_tf32(v23.y);
                const int b  = r >> 11;
                const int h  = cc >> 6;
                const int d0 = cc & (DK - 1);
                const size_t bx = ((size_t)(b * NHEAD + h) * SEQ);
                *(float2*)(C + (bx + (r & (SEQ - 1)))       * DK + d0) = v01;
                *(float2*)(C + (bx + ((r + 8) & (SEQ - 1))) * DK + d0) = v23;
            } else {
                *(float2*)(C + (size_t)r * D_MODEL + cc)       = v01;
                *(float2*)(C + (size_t)(r + 8) * D_MODEL + cc) = v23;
            }
        }
    }
}

// ---------------------------------------------------------------------------
// Flash attention on mma.sync tf32 (unchanged from the 1380us passing round).
// ---------------------------------------------------------------------------
#define FQ_STR 68
#define FK_STR 68
#define FV_STR 72
#define FP_STR 68
#define F_SQ   0
#define F_SK   (128 * FQ_STR)                     // 8704
#define F_SV   (F_SK + 2 * 64 * FK_STR)           // 17408
#define F_SP   (F_SV + 2 * 64 * FV_STR)           // 26624
#define F_TOT  (F_SP + 128 * FP_STR)              // 35328 floats = 141312 B

__global__ void __launch_bounds__(256) flash_tf32(
    const float* __restrict__ Q, const float* __restrict__ Kg,
    const float* __restrict__ V, float* __restrict__ O)
{
    extern __shared__ float sm[];
    float* sQ = sm + F_SQ;
    float* sK = sm + F_SK;
    float* sV = sm + F_SV;
    float* sP = sm + F_SP;

    const int tid = threadIdx.x;
    const int wid = tid >> 5;
    const int lid = tid & 31;
    const int grp = lid >> 2;     // 0..7
    const int tig = lid & 3;      // 0..3
    const int bh = blockIdx.y;
    const int q0 = blockIdx.x * 128;
    const int rb = wid * 16;      // warp's q-row base within tile

    const float* Qp = Q  + ((size_t)bh * SEQ + q0) * DK;
    const float* Kp = Kg + (size_t)bh * SEQ * DK;
    const float* Vp = V  + (size_t)bh * SEQ * DK;

    const uint32_t sQa = smem_u32(sQ);
    const uint32_t sKa = smem_u32(sK);
    const uint32_t sVa = smem_u32(sV);

    {
        const int r  = tid >> 1;
        const int c0 = (tid & 1) * 32;
#pragma unroll
        for (int j = 0; j < 8; j++)
            cp_async16(sQa + (uint32_t)(r * FQ_STR + c0 + j * 4) * 4,
                       Qp + (size_t)r * DK + c0 + j * 4);
    }
    {
        const int r  = tid >> 2;
        const int c0 = (tid & 3) * 16;
#pragma unroll
        for (int j = 0; j < 4; j++)
            cp_async16(sKa + (uint32_t)(r * FK_STR + c0 + j * 4) * 4,
                       Kp + (size_t)r * DK + c0 + j * 4);
#pragma unroll
        for (int j = 0; j < 4; j++)
            cp_async16(sVa + (uint32_t)(r * FV_STR + c0 + j * 4) * 4,
                       Vp + (size_t)r * DK + c0 + j * 4);
    }
    CP_COMMIT();

    float m0 = -1e30f, m1 = -1e30f, l0 = 0.0f, l1 = 0.0f;
    float oacc[8][4];
#pragma unroll
    for (int nt = 0; nt < 8; nt++)
#pragma unroll
        for (int j = 0; j < 4; j++) oacc[nt][j] = 0.0f;

    const float scale = 0.125f;   // 1/sqrt(64)
    const int NT = SEQ / 64;      // 32

#pragma unroll 1
    for (int t = 0; t < NT; t++) {
        const int s = t & 1;
        if (t + 1 < NT) {
            const int ns = s ^ 1;
            const int r  = tid >> 2;
            const int c0 = (tid & 3) * 16;
            const float* Kt = Kp + (size_t)(t + 1) * 64 * DK;
            const float* Vt = Vp + (size_t)(t + 1) * 64 * DK;
#pragma unroll
            for (int j = 0; j < 4; j++)
                cp_async16(sKa + (uint32_t)(ns * 64 * FK_STR + r * FK_STR + c0 + j * 4) * 4,
                           Kt + (size_t)r * DK + c0 + j * 4);
#pragma unroll
            for (int j = 0; j < 4; j++)
                cp_async16(sVa + (uint32_t)(ns * 64 * FV_STR + r * FV_STR + c0 + j * 4) * 4,
                           Vt + (size_t)r * DK + c0 + j * 4);
            CP_COMMIT();
            CP_WAIT(1);
        } else {
            CP_WAIT(0);
        }
        __syncthreads();

        const float* Kb = sK + s * 64 * FK_STR;
        const float* Vb = sV + s * 64 * FV_STR;

        // ---- S = scale * Q K^T -------------------------------------------
        float sf[8][4];
#pragma unroll
        for (int nt = 0; nt < 8; nt++)
#pragma unroll
            for (int j = 0; j < 4; j++) sf[nt][j] = 0.0f;

#pragma unroll
        for (int kb = 0; kb < 64; kb += 8) {
            float aq[4];
            aq[0] = sQ[(rb + grp)     * FQ_STR + kb + tig];
            aq[1] = sQ[(rb + grp + 8) * FQ_STR + kb + tig];
            aq[2] = sQ[(rb + grp)     * FQ_STR + kb + tig + 4];
            aq[3] = sQ[(rb + grp + 8) * FQ_STR + kb + tig + 4];
#pragma unroll
            for (int nt = 0; nt < 8; nt++) {
                float bk[2];
                bk[0] = Kb[(nt * 8 + grp) * FK_STR + kb + tig];
                bk[1] = Kb[(nt * 8 + grp) * FK_STR + kb + tig + 4];
                mma_tf32(sf[nt], aq, bk);
            }
        }

        // ---- online softmax ----------------------------------------------
        float mx0 = -1e30f, mx1 = -1e30f;
#pragma unroll
        for (int nt = 0; nt < 8; nt++) {
#pragma unroll
            for (int j = 0; j < 4; j++) sf[nt][j] *= scale;
            mx0 = fmaxf(mx0, fmaxf(sf[nt][0], sf[nt][1]));
            mx1 = fmaxf(mx1, fmaxf(sf[nt][2], sf[nt][3]));
        }
        mx0 = fmaxf(mx0, __shfl_xor_sync(0xffffffffu, mx0, 1, 4));
        mx0 = fmaxf(mx0, __shfl_xor_sync(0xffffffffu, mx0, 2, 4));
        mx1 = fmaxf(mx1, __shfl_xor_sync(0xffffffffu, mx1, 1, 4));
        mx1 = fmaxf(mx1, __shfl_xor_sync(0xffffffffu, mx1, 2, 4));

        const float mn0 = fmaxf(m0, mx0);
        const float mn1 = fmaxf(m1, mx1);
        const float a0 = __expf(m0 - mn0);
        const float a1 = __expf(m1 - mn1);
        m0 = mn0; m1 = mn1;

        float rs0 = 0.0f, rs1 = 0.0f;
#pragma unroll
        for (int nt = 0; nt < 8; nt++) {
            const float p00 = rna_tf32(__expf(sf[nt][0] - mn0));
            const float p01 = rna_tf32(__expf(sf[nt][1] - mn0));
            const float p10 = rna_tf32(__expf(sf[nt][2] - mn1));
            const float p11 = rna_tf32(__expf(sf[nt][3] - mn1));
            rs0 += p00 + p01;
            rs1 += p10 + p11;
            *(float2*)&sP[(rb + grp)     * FP_STR + nt * 8 + 2 * tig] = make_float2(p00, p01);
            *(float2*)&sP[(rb + grp + 8) * FP_STR + nt * 8 + 2 * tig] = make_float2(p10, p11);
        }
        rs0 += __shfl_xor_sync(0xffffffffu, rs0, 1, 4);
        rs0 += __shfl_xor_sync(0xffffffffu, rs0, 2, 4);
        rs1 += __shfl_xor_sync(0xffffffffu, rs1, 1, 4);
        rs1 += __shfl_xor_sync(0xffffffffu, rs1, 2, 4);
        l0 = l0 * a0 + rs0;
        l1 = l1 * a1 + rs1;

#pragma unroll
        for (int nt = 0; nt < 8; nt++) {
            oacc[nt][0] *= a0; oacc[nt][1] *= a0;
            oacc[nt][2] *= a1; oacc[nt][3] *= a1;
        }
        __syncthreads();

        // ---- O += P V ----------------------------------------------------
#pragma unroll
        for (int kb = 0; kb < 64; kb += 8) {
            float ap[4];
            ap[0] = sP[(rb + grp)     * FP_STR + kb + tig];
            ap[1] = sP[(rb + grp + 8) * FP_STR + kb + tig];
            ap[2] = sP[(rb + grp)     * FP_STR + kb + tig + 4];
            ap[3] = sP[(rb + grp + 8) * FP_STR + kb + tig + 4];
#pragma unroll
            for (int nt = 0; nt < 8; nt++) {
                float bv[2];
                bv[0] = Vb[(kb + tig)     * FV_STR + nt * 8 + grp];
                bv[1] = Vb[(kb + tig + 4) * FV_STR + nt * 8 + grp];
                mma_tf32(oacc[nt], ap, bv);
            }
        }
        __syncthreads();
    }

    // ---- epilogue: O /= l, RNA-round, write [B,n,D_MODEL] ----------------
    const int b = bh >> 4;
    const int h = bh & (NHEAD - 1);
    const int r0g = q0 + rb + grp;
    const int r1g = r0g + 8;
    const float inv0 = 1.0f / l0;
    const float inv1 = 1.0f / l1;
#pragma unroll
    for (int nt = 0; nt < 8; nt++) {
        float2 v0 = make_float2(rna_tf32(oacc[nt][0] * inv0), rna_tf32(oacc[nt][1] * inv0));
        float2 v1 = make_float2(rna_tf32(oacc[nt][2] * inv1), rna_tf32(oacc[nt][3] * inv1));
        const int cc = h * DK + nt * 8 + 2 * tig;
        *(float2*)(O + ((size_t)b * SEQ + r0g) * D_MODEL + cc) = v0;
        *(float2*)(O + ((size_t)b * SEQ + r1g) * D_MODEL + cc) = v1;
    }
}

// ---------------------------------------------------------------------------
extern "C" void kernel_launch(void* const* d_in, const int* in_sizes, int n_in,
                              void* d_out, int out_size)
{
    const float* X  = (const float*)d_in[0];
    const float* Wq = (const float*)d_in[1];
    const float* bq = (const float*)d_in[2];
    const float* Wk = (const float*)d_in[3];
    const float* bk = (const float*)d_in[4];
    const float* Wv = (const float*)d_in[5];
    const float* bv = (const float*)d_in[6];
    const float* Wo = (const float*)d_in[7];
    const float* bo = (const float*)d_in[8];
    float* out = (float*)d_out;

    float *Qp, *Kp, *Vp, *AOp, *Xc, *Wqc, *Wkc, *Wvc, *Woc;
    cudaGetSymbolAddress((void**)&Qp,  g_Q);
    cudaGetSymbolAddress((void**)&Kp,  g_K);
    cudaGetSymbolAddress((void**)&Vp,  g_V);
    cudaGetSymbolAddress((void**)&AOp, g_AO);
    cudaGetSymbolAddress((void**)&Xc,  g_Xc);
    cudaGetSymbolAddress((void**)&Wqc, g_Wqc);
    cudaGetSymbolAddress((void**)&Wkc, g_Wkc);
    cudaGetSymbolAddress((void**)&Wvc, g_Wvc);
    cudaGetSymbolAddress((void**)&Woc, g_Woc);

    // --- unbiased tf32 pre-rounding of GEMM inputs ---
    const int nX4 = MROWS * D_MODEL / 4;        // 2097152
    const int nW4 = D_MODEL * D_MODEL / 4;      // 262144
    round_tf32<<<nX4 / 256, 256>>>(X,  Xc,  nX4);
    round_tf32<<<nW4 / 256, 256>>>(Wq, Wqc, nW4);
    round_tf32<<<nW4 / 256, 256>>>(Wk, Wkc, nW4);
    round_tf32<<<nW4 / 256, 256>>>(Wv, Wvc, nW4);
    round_tf32<<<nW4 / 256, 256>>>(Wo, Woc, nW4);

    // --- QKV projections on tensor cores (HMMA tf32); outputs RNA-rounded ---
    cudaFuncSetAttribute(gemm_tf32mma<true>,
                         cudaFuncAttributeMaxDynamicSharedMemorySize, G_SMEM);
    cudaFuncSetAttribute(gemm_tf32mma<false>,
                         cudaFuncAttributeMaxDynamicSharedMemorySize, G_SMEM);
    dim3 gg(D_MODEL / 128, MROWS / 128);   // (8, 64)
    gemm_tf32mma<true><<<gg, 128, G_SMEM>>>(Xc, Wqc, bq, Qp);
    gemm_tf32mma<true><<<gg, 128, G_SMEM>>>(Xc, Wkc, bk, Kp);
    gemm_tf32mma<true><<<gg, 128, G_SMEM>>>(Xc, Wvc, bv, Vp);

    // --- attention on tensor cores (tf32); output RNA-rounded in epilogue ---
    const int fsmem = F_TOT * 4;   // 141312
    cudaFuncSetAttribute(flash_tf32, cudaFuncAttributeMaxDynamicSharedMemorySize, fsmem);
    flash_tf32<<<dim3(SEQ / 128, BATCH * NHEAD), 256, fsmem>>>(Qp, Kp, Vp, AOp);

    // --- output projection ---
    gemm_tf32mma<false><<<gg, 128, G_SMEM>>>(AOp, Woc, bo, out);
}

// round 14
// speedup vs baseline: 1.1614x; 1.1614x over previous
#include <cuda_runtime.h>
#include <cstdint>

#define D_MODEL 1024
#define NHEAD   16
#define DK      64
#define SEQ     2048
#define BATCH   4
#define MROWS   (BATCH * SEQ)   // 8192

// ---------------------------------------------------------------------------
// Scratch (allocation-free rule: __device__ globals)
// ---------------------------------------------------------------------------
__device__ float g_Q[BATCH * NHEAD * SEQ * DK];   // [B,H,n,dk], tf32-rounded
__device__ float g_K[BATCH * NHEAD * SEQ * DK];
__device__ float g_V[BATCH * NHEAD * SEQ * DK];
__device__ float g_AO[BATCH * SEQ * D_MODEL];     // attention out, [B,n,D], tf32-rounded
__device__ float g_Xc[MROWS * D_MODEL];           // tf32-rounded X
__device__ float g_Wqc[D_MODEL * D_MODEL];
__device__ float g_Wkc[D_MODEL * D_MODEL];
__device__ float g_Wvc[D_MODEL * D_MODEL];
__device__ float g_Woc[D_MODEL * D_MODEL];

// ---------------------------------------------------------------------------
// helpers
// ---------------------------------------------------------------------------
__device__ __forceinline__ uint32_t smem_u32(const void* p) {
    uint32_t a;
    asm("{ .reg .u64 t; cvta.to.shared.u64 t, %1; cvt.u32.u64 %0, t; }"
        : "=r"(a) : "l"(p));
    return a;
}

__device__ __forceinline__ void cp_async16(uint32_t dst, const void* src) {
    asm volatile("cp.async.cg.shared.global [%0], [%1], 16;\n" :: "r"(dst), "l"(src));
}
#define CP_COMMIT()  asm volatile("cp.async.commit_group;\n" ::: "memory")
#define CP_WAIT(N)   asm volatile("cp.async.wait_group %0;\n" :: "n"(N) : "memory")

__device__ __forceinline__ void mma_tf32(float* c, const float* a, const float* b) {
    asm volatile(
        "mma.sync.aligned.m16n8k8.row.col.f32.tf32.tf32.f32 "
        "{%0,%1,%2,%3}, {%4,%5,%6,%7}, {%8,%9}, {%0,%1,%2,%3};"
        : "+f"(c[0]), "+f"(c[1]), "+f"(c[2]), "+f"(c[3])
        : "r"(__float_as_uint(a[0])), "r"(__float_as_uint(a[1])),
          "r"(__float_as_uint(a[2])), "r"(__float_as_uint(a[3])),
          "r"(__float_as_uint(b[0])), "r"(__float_as_uint(b[1])));
}

__device__ __forceinline__ float rna_tf32(float x) {
    uint32_t u;
    asm("cvt.rna.tf32.f32 %0, %1;" : "=r"(u) : "f"(x));
    return __uint_as_float(u);
}

// ---------------------------------------------------------------------------
// Elementwise tf32 RNA rounding (unbiased).
// ---------------------------------------------------------------------------
__global__ void round_tf32(const float* __restrict__ in, float* __restrict__ out, int n4) {
    int i = blockIdx.x * blockDim.x + threadIdx.x;
    if (i < n4) {
        float4 v = ((const float4*)in)[i];
        float4 o;
        o.x = rna_tf32(v.x); o.y = rna_tf32(v.y);
        o.z = rna_tf32(v.z); o.w = rna_tf32(v.w);
        ((float4*)out)[i] = o;
    }
}

// One launch rounds all 4 weight matrices (z selects).
__global__ void round_tf32_w4(
    const float* __restrict__ w0, const float* __restrict__ w1,
    const float* __restrict__ w2, const float* __restrict__ w3,
    float* __restrict__ o0, float* __restrict__ o1,
    float* __restrict__ o2, float* __restrict__ o3, int n4)
{
    const int z = blockIdx.y;
    const float* in  = (z == 0) ? w0 : (z == 1) ? w1 : (z == 2) ? w2 : w3;
    float*       out = (z == 0) ? o0 : (z == 1) ? o1 : (z == 2) ? o2 : o3;
    int i = blockIdx.x * blockDim.x + threadIdx.x;
    if (i < n4) {
        float4 v = ((const float4*)in)[i];
        float4 o;
        o.x = rna_tf32(v.x); o.y = rna_tf32(v.y);
        o.z = rna_tf32(v.z); o.w = rna_tf32(v.w);
        ((float4*)out)[i] = o;
    }
}

// ---------------------------------------------------------------------------
// TN GEMM core on mma.sync tf32: C[m,n] = sum_k A[m,k] * W[n,k] + bias[n]
// EXACT round-3 (1380us) configuration: CTA tile 128x128, BK=16, 256 threads
// (8 warps 2x4, warp tile 64x32), double-buffered cp.async, PAD 20 smem.
// ---------------------------------------------------------------------------
#define PAD 20

template <bool HEADOUT>
__device__ __forceinline__ void gemm_core(
    const float* __restrict__ A, const float* __restrict__ W,
    const float* __restrict__ bias, float* __restrict__ C)
{
    __shared__ float sA[2][128 * PAD];
    __shared__ float sB[2][128 * PAD];

    const int K = D_MODEL;
    const int tid = threadIdx.x;
    const int wid = tid >> 5;
    const int lid = tid & 31;
    const int warpM = wid >> 2;          // 0..1
    const int warpN = wid & 3;           // 0..3
    const int grp = lid >> 2;            // 0..7
    const int tig = lid & 3;             // 0..3
    const int row0 = blockIdx.y * 128;
    const int col0 = blockIdx.x * 128;

    const float* Ag = A + (size_t)row0 * K;
    const float* Wg = W + (size_t)col0 * K;

    const uint32_t aBase = smem_u32(sA);
    const uint32_t bBase = smem_u32(sB);

    const int lr = tid >> 1;
    const int lc = (tid & 1) * 8;
    const uint32_t ldst = (uint32_t)(lr * PAD + lc) * 4;

    float acc[4][4][4];
#pragma unroll
    for (int mt = 0; mt < 4; mt++)
#pragma unroll
        for (int nt = 0; nt < 4; nt++)
#pragma unroll
            for (int j = 0; j < 4; j++) acc[mt][nt][j] = 0.0f;

    {
        cp_async16(aBase + ldst,      Ag + (size_t)lr * K + lc);
        cp_async16(aBase + ldst + 16, Ag + (size_t)lr * K + lc + 4);
        cp_async16(bBase + ldst,      Wg + (size_t)lr * K + lc);
        cp_async16(bBase + ldst + 16, Wg + (size_t)lr * K + lc + 4);
        CP_COMMIT();
    }

    const int NC = K / 16;   // 64
#pragma unroll 1
    for (int c = 0; c < NC; c++) {
        const int s = c & 1;
        if (c + 1 < NC) {
            const uint32_t soff = (uint32_t)((s ^ 1) * 128 * PAD) * 4;
            const int k0 = (c + 1) * 16;
            cp_async16(aBase + soff + ldst,      Ag + (size_t)lr * K + k0 + lc);
            cp_async16(aBase + soff + ldst + 16, Ag + (size_t)lr * K + k0 + lc + 4);
            cp_async16(bBase + soff + ldst,      Wg + (size_t)lr * K + k0 + lc);
            cp_async16(bBase + soff + ldst + 16, Wg + (size_t)lr * K + k0 + lc + 4);
            CP_COMMIT();
            CP_WAIT(1);
        } else {
            CP_WAIT(0);
        }
        __syncthreads();

        const float* Ab = sA[s];
        const float* Bb = sB[s];
#pragma unroll
        for (int ks = 0; ks < 2; ks++) {
            const int kb = ks * 8;
            float af[4][4];
#pragma unroll
            for (int mt = 0; mt < 4; mt++) {
                const int rb = warpM * 64 + mt * 16;
                af[mt][0] = Ab[(rb + grp)     * PAD + kb + tig];
                af[mt][1] = Ab[(rb + grp + 8) * PAD + kb + tig];
                af[mt][2] = Ab[(rb + grp)     * PAD + kb + tig + 4];
                af[mt][3] = Ab[(rb + grp + 8) * PAD + kb + tig + 4];
            }
            float bf[4][2];
#pragma unroll
            for (int nt = 0; nt < 4; nt++) {
                const int cb = warpN * 32 + nt * 8;
                bf[nt][0] = Bb[(cb + grp) * PAD + kb + tig];
                bf[nt][1] = Bb[(cb + grp) * PAD + kb + tig + 4];
            }
#pragma unroll
            for (int mt = 0; mt < 4; mt++)
#pragma unroll
                for (int nt = 0; nt < 4; nt++)
                    mma_tf32(acc[mt][nt], af[mt], bf[nt]);
        }
        __syncthreads();
    }

#pragma unroll
    for (int mt = 0; mt < 4; mt++) {
#pragma unroll
        for (int nt = 0; nt < 4; nt++) {
            const int r  = row0 + warpM * 64 + mt * 16 + grp;
            const int cc = col0 + warpN * 32 + nt * 8 + tig * 2;
            const float b0 = bias[cc], b1 = bias[cc + 1];

            float2 v01 = make_float2(acc[mt][nt][0] + b0, acc[mt][nt][1] + b1);
            float2 v23 = make_float2(acc[mt][nt][2] + b0, acc[mt][nt][3] + b1);

            if (HEADOUT) {
                // RNA-round so flash's tf32 mma truncation is exact.
                v01.x = rna_tf32(v01.x); v01.y = rna_tf32(v01.y);
                v23.x = rna_tf32(v23.x); v23.y = rna_tf32(v23.y);
                const int b  = r >> 11;
                const int h  = cc >> 6;
                const int d0 = cc & (DK - 1);
                const size_t base = ((size_t)(b * NHEAD + h) * SEQ);
                *(float2*)(C + (base + (r & (SEQ - 1)))     * DK + d0) = v01;
                *(float2*)(C + (base + ((r + 8) & (SEQ-1))) * DK + d0) = v23;
            } else {
                *(float2*)(C + (size_t)r * D_MODEL + cc)       = v01;
                *(float2*)(C + (size_t)(r + 8) * D_MODEL + cc) = v23;
            }
        }
    }
}

// Fused QKV: one launch, blockIdx.z selects which projection this CTA does.
__global__ void __launch_bounds__(256) gemm_qkv(
    const float* __restrict__ A,
    const float* __restrict__ W0, const float* __restrict__ W1, const float* __restrict__ W2,
    const float* __restrict__ b0, const float* __restrict__ b1, const float* __restrict__ b2,
    float* __restrict__ C0, float* __restrict__ C1, float* __restrict__ C2)
{
    const int z = blockIdx.z;
    const float* W  = (z == 0) ? W0 : (z == 1) ? W1 : W2;
    const float* bi = (z == 0) ? b0 : (z == 1) ? b1 : b2;
    float*       C  = (z == 0) ? C0 : (z == 1) ? C1 : C2;
    gemm_core<true>(A, W, bi, C);
}

__global__ void __launch_bounds__(256) gemm_out(
    const float* __restrict__ A, const float* __restrict__ W,
    const float* __restrict__ bias, float* __restrict__ C)
{
    gemm_core<false>(A, W, bias, C);
}

// ---------------------------------------------------------------------------
// Flash attention on mma.sync tf32 (unchanged; O RNA-rounded in epilogue).
// ---------------------------------------------------------------------------
#define FQ_STR 68
#define FK_STR 68
#define FV_STR 72
#define FP_STR 68
#define F_SQ   0
#define F_SK   (128 * FQ_STR)                     // 8704
#define F_SV   (F_SK + 2 * 64 * FK_STR)           // 17408
#define F_SP   (F_SV + 2 * 64 * FV_STR)           // 26624
#define F_TOT  (F_SP + 128 * FP_STR)              // 35328 floats = 141312 B

__global__ void __launch_bounds__(256) flash_tf32(
    const float* __restrict__ Q, const float* __restrict__ Kg,
    const float* __restrict__ V, float* __restrict__ O)
{
    extern __shared__ float sm[];
    float* sQ = sm + F_SQ;
    float* sK = sm + F_SK;
    float* sV = sm + F_SV;
    float* sP = sm + F_SP;

    const int tid = threadIdx.x;
    const int wid = tid >> 5;
    const int lid = tid & 31;
    const int grp = lid >> 2;     // 0..7
    const int tig = lid & 3;      // 0..3
    const int bh = blockIdx.y;
    const int q0 = blockIdx.x * 128;
    const int rb = wid * 16;      // warp's q-row base within tile

    const float* Qp = Q  + ((size_t)bh * SEQ + q0) * DK;
    const float* Kp = Kg + (size_t)bh * SEQ * DK;
    const float* Vp = V  + (size_t)bh * SEQ * DK;

    const uint32_t sQa = smem_u32(sQ);
    const uint32_t sKa = smem_u32(sK);
    const uint32_t sVa = smem_u32(sV);

    {
        const int r  = tid >> 1;
        const int c0 = (tid & 1) * 32;
#pragma unroll
        for (int j = 0; j < 8; j++)
            cp_async16(sQa + (uint32_t)(r * FQ_STR + c0 + j * 4) * 4,
                       Qp + (size_t)r * DK + c0 + j * 4);
    }
    {
        const int r  = tid >> 2;
        const int c0 = (tid & 3) * 16;
#pragma unroll
        for (int j = 0; j < 4; j++)
            cp_async16(sKa + (uint32_t)(r * FK_STR + c0 + j * 4) * 4,
                       Kp + (size_t)r * DK + c0 + j * 4);
#pragma unroll
        for (int j = 0; j < 4; j++)
            cp_async16(sVa + (uint32_t)(r * FV_STR + c0 + j * 4) * 4,
                       Vp + (size_t)r * DK + c0 + j * 4);
    }
    CP_COMMIT();

    float m0 = -1e30f, m1 = -1e30f, l0 = 0.0f, l1 = 0.0f;
    float oacc[8][4];
#pragma unroll
    for (int nt = 0; nt < 8; nt++)
#pragma unroll
        for (int j = 0; j < 4; j++) oacc[nt][j] = 0.0f;

    const float scale = 0.125f;   // 1/sqrt(64)
    const int NT = SEQ / 64;      // 32

#pragma unroll 1
    for (int t = 0; t < NT; t++) {
        const int s = t & 1;
        if (t + 1 < NT) {
            const int ns = s ^ 1;
            const int r  = tid >> 2;
            const int c0 = (tid & 3) * 16;
            const float* Kt = Kp + (size_t)(t + 1) * 64 * DK;
            const float* Vt = Vp + (size_t)(t + 1) * 64 * DK;
#pragma unroll
            for (int j = 0; j < 4; j++)
                cp_async16(sKa + (uint32_t)(ns * 64 * FK_STR + r * FK_STR + c0 + j * 4) * 4,
                           Kt + (size_t)r * DK + c0 + j * 4);
#pragma unroll
            for (int j = 0; j < 4; j++)
                cp_async16(sVa + (uint32_t)(ns * 64 * FV_STR + r * FV_STR + c0 + j * 4) * 4,
                           Vt + (size_t)r * DK + c0 + j * 4);
            CP_COMMIT();
            CP_WAIT(1);
        } else {
            CP_WAIT(0);
        }
        __syncthreads();

        const float* Kb = sK + s * 64 * FK_STR;
        const float* Vb = sV + s * 64 * FV_STR;

        // ---- S = scale * Q K^T -------------------------------------------
        float sf[8][4];
#pragma unroll
        for (int nt = 0; nt < 8; nt++)
#pragma unroll
            for (int j = 0; j < 4; j++) sf[nt][j] = 0.0f;

#pragma unroll
        for (int kb = 0; kb < 64; kb += 8) {
            float aq[4];
            aq[0] = sQ[(rb + grp)     * FQ_STR + kb + tig];
            aq[1] = sQ[(rb + grp + 8) * FQ_STR + kb + tig];
            aq[2] = sQ[(rb + grp)     * FQ_STR + kb + tig + 4];
            aq[3] = sQ[(rb + grp + 8) * FQ_STR + kb + tig + 4];
#pragma unroll
            for (int nt = 0; nt < 8; nt++) {
                float bk[2];
                bk[0] = Kb[(nt * 8 + grp) * FK_STR + kb + tig];
                bk[1] = Kb[(nt * 8 + grp) * FK_STR + kb + tig + 4];
                mma_tf32(sf[nt], aq, bk);
            }
        }

        // ---- online softmax ----------------------------------------------
        float mx0 = -1e30f, mx1 = -1e30f;
#pragma unroll
        for (int nt = 0; nt < 8; nt++) {
#pragma unroll
            for (int j = 0; j < 4; j++) sf[nt][j] *= scale;
            mx0 = fmaxf(mx0, fmaxf(sf[nt][0], sf[nt][1]));
            mx1 = fmaxf(mx1, fmaxf(sf[nt][2], sf[nt][3]));
        }
        mx0 = fmaxf(mx0, __shfl_xor_sync(0xffffffffu, mx0, 1, 4));
        mx0 = fmaxf(mx0, __shfl_xor_sync(0xffffffffu, mx0, 2, 4));
        mx1 = fmaxf(mx1, __shfl_xor_sync(0xffffffffu, mx1, 1, 4));
        mx1 = fmaxf(mx1, __shfl_xor_sync(0xffffffffu, mx1, 2, 4));

        const float mn0 = fmaxf(m0, mx0);
        const float mn1 = fmaxf(m1, mx1);
        const float a0 = __expf(m0 - mn0);
        const float a1 = __expf(m1 - mn1);
        m0 = mn0; m1 = mn1;

        float rs0 = 0.0f, rs1 = 0.0f;
#pragma unroll
        for (int nt = 0; nt < 8; nt++) {
            const float p00 = rna_tf32(__expf(sf[nt][0] - mn0));
            const float p01 = rna_tf32(__expf(sf[nt][1] - mn0));
            const float p10 = rna_tf32(__expf(sf[nt][2] - mn1));
            const float p11 = rna_tf32(__expf(sf[nt][3] - mn1));
            rs0 += p00 + p01;
            rs1 += p10 + p11;
            *(float2*)&sP[(rb + grp)     * FP_STR + nt * 8 + 2 * tig] = make_float2(p00, p01);
            *(float2*)&sP[(rb + grp + 8) * FP_STR + nt * 8 + 2 * tig] = make_float2(p10, p11);
        }
        rs0 += __shfl_xor_sync(0xffffffffu, rs0, 1, 4);
        rs0 += __shfl_xor_sync(0xffffffffu, rs0, 2, 4);
        rs1 += __shfl_xor_sync(0xffffffffu, rs1, 1, 4);
        rs1 += __shfl_xor_sync(0xffffffffu, rs1, 2, 4);
        l0 = l0 * a0 + rs0;
        l1 = l1 * a1 + rs1;

#pragma unroll
        for (int nt = 0; nt < 8; nt++) {
            oacc[nt][0] *= a0; oacc[nt][1] *= a0;
            oacc[nt][2] *= a1; oacc[nt][3] *= a1;
        }
        __syncthreads();

        // ---- O += P V ----------------------------------------------------
#pragma unroll
        for (int kb = 0; kb < 64; kb += 8) {
            float ap[4];
            ap[0] = sP[(rb + grp)     * FP_STR + kb + tig];
            ap[1] = sP[(rb + grp + 8) * FP_STR + kb + tig];
            ap[2] = sP[(rb + grp)     * FP_STR + kb + tig + 4];
            ap[3] = sP[(rb + grp + 8) * FP_STR + kb + tig + 4];
#pragma unroll
            for (int nt = 0; nt < 8; nt++) {
                float bv[2];
                bv[0] = Vb[(kb + tig)     * FV_STR + nt * 8 + grp];
                bv[1] = Vb[(kb + tig + 4) * FV_STR + nt * 8 + grp];
                mma_tf32(oacc[nt], ap, bv);
            }
        }
        __syncthreads();
    }

    // ---- epilogue: O /= l, RNA-round, write [B,n,D_MODEL] ----------------
    const int b = bh >> 4;
    const int h = bh & (NHEAD - 1);
    const int r0g = q0 + rb + grp;
    const int r1g = r0g + 8;
    const float inv0 = 1.0f / l0;
    const float inv1 = 1.0f / l1;
#pragma unroll
    for (int nt = 0; nt < 8; nt++) {
        float2 v0 = make_float2(rna_tf32(oacc[nt][0] * inv0), rna_tf32(oacc[nt][1] * inv0));
        float2 v1 = make_float2(rna_tf32(oacc[nt][2] * inv1), rna_tf32(oacc[nt][3] * inv1));
        const int cc = h * DK + nt * 8 + 2 * tig;
        *(float2*)(O + ((size_t)b * SEQ + r0g) * D_MODEL + cc) = v0;
        *(float2*)(O + ((size_t)b * SEQ + r1g) * D_MODEL + cc) = v1;
    }
}

// ---------------------------------------------------------------------------
extern "C" void kernel_launch(void* const* d_in, const int* in_sizes, int n_in,
                              void* d_out, int out_size)
{
    const float* X  = (const float*)d_in[0];
    const float* Wq = (const float*)d_in[1];
    const float* bq = (const float*)d_in[2];
    const float* Wk = (const float*)d_in[3];
    const float* bk = (const float*)d_in[4];
    const float* Wv = (const float*)d_in[5];
    const float* bv = (const float*)d_in[6];
    const float* Wo = (const float*)d_in[7];
    const float* bo = (const float*)d_in[8];
    float* out = (float*)d_out;

    float *Qp, *Kp, *Vp, *AOp, *Xc, *Wqc, *Wkc, *Wvc, *Woc;
    cudaGetSymbolAddress((void**)&Qp,  g_Q);
    cudaGetSymbolAddress((void**)&Kp,  g_K);
    cudaGetSymbolAddress((void**)&Vp,  g_V);
    cudaGetSymbolAddress((void**)&AOp, g_AO);
    cudaGetSymbolAddress((void**)&Xc,  g_Xc);
    cudaGetSymbolAddress((void**)&Wqc, g_Wqc);
    cudaGetSymbolAddress((void**)&Wkc, g_Wkc);
    cudaGetSymbolAddress((void**)&Wvc, g_Wvc);
    cudaGetSymbolAddress((void**)&Woc, g_Woc);

    // --- unbiased tf32 pre-rounding: X (1 launch) + 4 weights (1 launch) ---
    const int nX4 = MROWS * D_MODEL / 4;        // 2097152
    const int nW4 = D_MODEL * D_MODEL / 4;      // 262144
    round_tf32<<<nX4 / 256, 256>>>(X, Xc, nX4);
    round_tf32_w4<<<dim3(nW4 / 256, 4), 256>>>(Wq, Wk, Wv, Wo,
                                               Wqc, Wkc, Wvc, Woc, nW4);

    // --- QKV projections: ONE fused launch (z selects projection) ---
    dim3 gq(D_MODEL / 128, MROWS / 128, 3);   // (8, 64, 3) = 1536 CTAs
    gemm_qkv<<<gq, 256>>>(Xc, Wqc, Wkc, Wvc, bq, bk, bv, Qp, Kp, Vp);

    // --- attention on tensor cores (tf32); O RNA-rounded in epilogue ---
    const int fsmem = F_TOT * 4;   // 141312
    cudaFuncSetAttribute(flash_tf32, cudaFuncAttributeMaxDynamicSharedMemorySize, fsmem);
    flash_tf32<<<dim3(SEQ / 128, BATCH * NHEAD), 256, fsmem>>>(Qp, Kp, Vp, AOp);

    // --- output projection ---
    dim3 gg(D_MODEL / 128, MROWS / 128);      // (8, 64)
    gemm_out<<<gg, 256>>>(AOp, Woc, bo, out);
}